// round 15
// baseline (speedup 1.0000x reference)
#include <cuda_runtime.h>
#include <cuda_fp16.h>
#include <math.h>
#include <stdint.h>

#define BSZ 2048
#define HDIM 4096

// ---------------------------------------------------------------------------
// Scratch (allocation-free: __device__ globals)
// ---------------------------------------------------------------------------
__device__ __align__(16) __half g_wfh [(size_t)2 * HDIM * HDIM];  // fp16 w_fused
__device__ __align__(16) __half g_wgh [(size_t)2 * HDIM * HDIM];  // fp16 w_gates
__device__ __align__(16) __half g_woh [(size_t)HDIM * HDIM];      // fp16 w_out
__device__ __align__(16) __half g_xh  [(size_t)BSZ * HDIM];       // fp16 x
__device__ __align__(16) __half g_xch [(size_t)BSZ * HDIM];       // fp16 x_conv
__device__ __align__(16) __half g_hh  [(size_t)BSZ * HDIM];       // fp16 gate*state
__device__ float g_fused[(size_t)BSZ * 2 * HDIM];   // x @ w_fused^T        (fp32)
__device__ float g_gate [(size_t)BSZ * HDIM];       // gelu(gate_out)       (fp32)
__device__ float g_xconv[(size_t)BSZ * HDIM];       // conv output          (fp32)
__device__ float g_gates[(size_t)BSZ * 2 * HDIM];   // x_conv @ w_gates^T   (fp32)

// ---------------------------------------------------------------------------
// Helpers
// ---------------------------------------------------------------------------
__device__ __forceinline__ void cp_async16(uint32_t sdst, const void* gsrc) {
    asm volatile("cp.async.ca.shared.global [%0], [%1], 16;\n" :: "r"(sdst), "l"(gsrc));
}
__device__ __forceinline__ void cp_commit() {
    asm volatile("cp.async.commit_group;\n");
}
template <int N>
__device__ __forceinline__ void cp_wait() {
    asm volatile("cp.async.wait_group %0;\n" :: "n"(N));
}

// ---------------------------------------------------------------------------
// FP16 tensor-core GEMM: C[M,N] = A[M,K] @ B[N,K]^T  (fp16 in, fp32 out)
// CTA tile 128x128, BK=32, 256 threads (8 warps 4x2), warp tile 32x64,
// mma.sync.m16n8k16.f32.f16.f16.f32, cp.async double buffering.
// smem stride 40 halves (80B): fragment loads verified bank-conflict-free.
// ---------------------------------------------------------------------------
#define BM 128
#define BN 128
#define BK 32
#define SH 40   // smem stride in halves

__global__ __launch_bounds__(256, 2)
void gemm_f16_nt(const __half* __restrict__ A,
                 const __half* __restrict__ Bm,
                 float* __restrict__ C,
                 int M, int N, int K)
{
    __shared__ __half As[2][BM * SH];
    __shared__ __half Bs[2][BN * SH];

    const int tid    = threadIdx.x;
    const int lane   = tid & 31;
    const int warpId = tid >> 5;
    const int warpRow = warpId & 3;   // 0..3  (32 rows each)
    const int warpCol = warpId >> 2;  // 0..1  (64 cols each)
    const int groupID = lane >> 2;    // 0..7
    const int tid4    = lane & 3;     // 0..3

    const size_t rowBase = (size_t)blockIdx.y * BM;
    const size_t colBase = (size_t)blockIdx.x * BN;

    const __half* Ab = A  + rowBase * K;
    const __half* Bb = Bm + colBase * K;

    float acc[2][8][4];
    #pragma unroll
    for (int m = 0; m < 2; m++)
        #pragma unroll
        for (int n = 0; n < 8; n++)
            #pragma unroll
            for (int v = 0; v < 4; v++)
                acc[m][n][v] = 0.0f;

    const int numTiles = K / BK;

    uint32_t sA_base = (uint32_t)__cvta_generic_to_shared(&As[0][0]);
    uint32_t sB_base = (uint32_t)__cvta_generic_to_shared(&Bs[0][0]);
    const uint32_t stage = (uint32_t)(BM * SH * sizeof(__half));   // same for A and B

    // Per 128x32-half tile: 128 rows x 4 chunks(16B) = 512 chunks; 2/thread.
    auto issue_loads = [&](int t, int buf) {
        const int k0 = t * BK;
        #pragma unroll
        for (int i = 0; i < 2; i++) {
            int c   = tid + i * 256;      // 0..511
            int row = c >> 2;
            int j   = c & 3;              // 16B chunk = 8 halves
            cp_async16(sA_base + buf * stage + (uint32_t)(row * SH + j * 8) * 2,
                       Ab + (size_t)row * K + k0 + j * 8);
            cp_async16(sB_base + buf * stage + (uint32_t)(row * SH + j * 8) * 2,
                       Bb + (size_t)row * K + k0 + j * 8);
        }
        cp_commit();
    };

    issue_loads(0, 0);

    for (int t = 0; t < numTiles; t++) {
        const int buf = t & 1;
        if (t + 1 < numTiles) {
            issue_loads(t + 1, buf ^ 1);
            cp_wait<1>();
        } else {
            cp_wait<0>();
        }
        __syncthreads();

        const __half* sA = &As[buf][0];
        const __half* sB = &Bs[buf][0];

        #pragma unroll
        for (int kk = 0; kk < 2; kk++) {
            const int k0 = kk * 16;
            uint32_t af[2][4];
            uint32_t bf[8][2];

            #pragma unroll
            for (int m = 0; m < 2; m++) {
                int r = warpRow * 32 + m * 16 + groupID;
                af[m][0] = *reinterpret_cast<const uint32_t*>(&sA[(r)     * SH + k0 + tid4 * 2]);
                af[m][1] = *reinterpret_cast<const uint32_t*>(&sA[(r + 8) * SH + k0 + tid4 * 2]);
                af[m][2] = *reinterpret_cast<const uint32_t*>(&sA[(r)     * SH + k0 + tid4 * 2 + 8]);
                af[m][3] = *reinterpret_cast<const uint32_t*>(&sA[(r + 8) * SH + k0 + tid4 * 2 + 8]);
            }
            #pragma unroll
            for (int n = 0; n < 8; n++) {
                int cidx = warpCol * 64 + n * 8 + groupID;
                bf[n][0] = *reinterpret_cast<const uint32_t*>(&sB[cidx * SH + k0 + tid4 * 2]);
                bf[n][1] = *reinterpret_cast<const uint32_t*>(&sB[cidx * SH + k0 + tid4 * 2 + 8]);
            }

            #pragma unroll
            for (int m = 0; m < 2; m++)
                #pragma unroll
                for (int n = 0; n < 8; n++) {
                    asm volatile(
                        "mma.sync.aligned.m16n8k16.row.col.f32.f16.f16.f32 "
                        "{%0,%1,%2,%3}, {%4,%5,%6,%7}, {%8,%9}, {%0,%1,%2,%3};\n"
                        : "+f"(acc[m][n][0]), "+f"(acc[m][n][1]),
                          "+f"(acc[m][n][2]), "+f"(acc[m][n][3])
                        : "r"(af[m][0]), "r"(af[m][1]), "r"(af[m][2]), "r"(af[m][3]),
                          "r"(bf[n][0]), "r"(bf[n][1]));
                }
        }
        __syncthreads();
    }

    // Epilogue: c0,c1 -> (row, tid4*2..+1), c2,c3 -> (row+8, ...)
    #pragma unroll
    for (int m = 0; m < 2; m++) {
        size_t r0 = rowBase + warpRow * 32 + m * 16 + groupID;
        #pragma unroll
        for (int n = 0; n < 8; n++) {
            size_t cc = colBase + warpCol * 64 + n * 8 + tid4 * 2;
            *reinterpret_cast<float2*>(C + r0 * N + cc)       = make_float2(acc[m][n][0], acc[m][n][1]);
            *reinterpret_cast<float2*>(C + (r0 + 8) * N + cc) = make_float2(acc[m][n][2], acc[m][n][3]);
        }
    }
}

// ---------------------------------------------------------------------------
// Convert fp32 -> fp16 (RN), 4 elements/thread
// ---------------------------------------------------------------------------
__global__ __launch_bounds__(256)
void cvt_f16_kernel(const float4* __restrict__ in, uint2* __restrict__ out, int n4)
{
    int i = blockIdx.x * blockDim.x + threadIdx.x;
    if (i >= n4) return;
    float4 v = in[i];
    __half2 h01 = __float22half2_rn(make_float2(v.x, v.y));
    __half2 h23 = __float22half2_rn(make_float2(v.z, v.w));
    uint2 o;
    o.x = *reinterpret_cast<uint32_t*>(&h01);
    o.y = *reinterpret_cast<uint32_t*>(&h23);
    out[i] = o;
}

// ---------------------------------------------------------------------------
// Elementwise 1: gelu gate, conv step, new_conv_state; fp16 copy of x_conv
// ---------------------------------------------------------------------------
__global__ __launch_bounds__(256)
void ew1_kernel(const float* __restrict__ conv_state,
                const float* __restrict__ conv_w,
                const float* __restrict__ conv_b,
                float* __restrict__ out_conv_state)
{
    size_t idx = (size_t)blockIdx.x * blockDim.x + threadIdx.x;
    if (idx >= (size_t)BSZ * HDIM) return;
    int b = (int)(idx / HDIM);
    int h = (int)(idx % HDIM);

    const size_t frow = (size_t)b * 2 * HDIM;
    float gate_out = g_fused[frow + h];
    float x_recur  = g_fused[frow + HDIM + h];

    float gate = gate_out * 0.5f * (1.0f + erff(gate_out * 0.70710678118654752f));

    const size_t csb = (size_t)b * HDIM * 3 + (size_t)h * 3;
    float c0 = conv_state[csb + 0];
    float c1 = conv_state[csb + 1];
    float c2 = conv_state[csb + 2];

    const float* w = conv_w + (size_t)h * 4;
    float xc = fmaf(c0, w[0], fmaf(c1, w[1], fmaf(c2, w[2], fmaf(x_recur, w[3], conv_b[h]))));

    g_gate[idx]  = gate;
    g_xconv[idx] = xc;
    g_xch[idx]   = __float2half_rn(xc);

    out_conv_state[csb + 0] = c1;
    out_conv_state[csb + 1] = c2;
    out_conv_state[csb + 2] = x_recur;
}

// ---------------------------------------------------------------------------
// Elementwise 2: RG-LRU update; h = gate*state written fp16 for GEMM3
// ---------------------------------------------------------------------------
__global__ __launch_bounds__(256)
void ew2_kernel(const float* __restrict__ rglru_state,
                const float* __restrict__ a_vec,
                float* __restrict__ out_rglru_state)
{
    size_t idx = (size_t)blockIdx.x * blockDim.x + threadIdx.x;
    if (idx >= (size_t)BSZ * HDIM) return;
    int b = (int)(idx / HDIM);
    int h = (int)(idx % HDIM);

    const size_t grow = (size_t)b * 2 * HDIM;
    float gi = g_gates[grow + h];
    float gr = g_gates[grow + HDIM + h];

    float i_t = 1.0f / (1.0f + expf(-gi));
    float r_t = 1.0f / (1.0f + expf(-gr));

    float log_a = logf(a_vec[h]);
    float a_t   = expf(8.0f * r_t * log_a);
    float mult  = sqrtf(fmaxf(0.0f, 1.0f - a_t * a_t));

    float xc = g_xconv[idx];
    float new_state = fmaf(rglru_state[idx], a_t, mult * (i_t * xc));

    out_rglru_state[idx] = new_state;
    g_hh[idx] = __float2half_rn(g_gate[idx] * new_state);
}

// ---------------------------------------------------------------------------
// kernel_launch
// inputs: x, conv_state, rglru_state, w_fused, conv_w, conv_b, w_gates, a, w_out
// output: concat(out[B,H], new_conv_state[B,H,3], new_rglru_state[B,H])
// ---------------------------------------------------------------------------
extern "C" void kernel_launch(void* const* d_in, const int* in_sizes, int n_in,
                              void* d_out, int out_size)
{
    const float* x           = (const float*)d_in[0];
    const float* conv_state  = (const float*)d_in[1];
    const float* rglru_state = (const float*)d_in[2];
    const float* w_fused     = (const float*)d_in[3];
    const float* conv_w      = (const float*)d_in[4];
    const float* conv_b      = (const float*)d_in[5];
    const float* w_gates     = (const float*)d_in[6];
    const float* a_vec       = (const float*)d_in[7];
    const float* w_out       = (const float*)d_in[8];

    float* out            = (float*)d_out;
    float* out_main       = out;                                  // (B, H)
    float* out_conv_state = out + (size_t)BSZ * HDIM;             // (B, H, 3)
    float* out_rglru      = out + (size_t)BSZ * HDIM * 4;         // (B, H)

    __half *p_wfh, *p_wgh, *p_woh, *p_xh, *p_xch, *p_hh;
    float  *p_fused, *p_gates;
    cudaGetSymbolAddress((void**)&p_wfh,   g_wfh);
    cudaGetSymbolAddress((void**)&p_wgh,   g_wgh);
    cudaGetSymbolAddress((void**)&p_woh,   g_woh);
    cudaGetSymbolAddress((void**)&p_xh,    g_xh);
    cudaGetSymbolAddress((void**)&p_xch,   g_xch);
    cudaGetSymbolAddress((void**)&p_hh,    g_hh);
    cudaGetSymbolAddress((void**)&p_fused, g_fused);
    cudaGetSymbolAddress((void**)&p_gates, g_gates);

    const int ewThreads = 256;
    const int ewBlocks  = (int)(((size_t)BSZ * HDIM + ewThreads - 1) / ewThreads);

    // Convert GEMM operands to fp16 (RN)
    {
        int n4w = 2 * HDIM * HDIM / 4;
        cvt_f16_kernel<<<(n4w + 255) / 256, 256>>>((const float4*)w_fused, (uint2*)p_wfh, n4w);
        cvt_f16_kernel<<<(n4w + 255) / 256, 256>>>((const float4*)w_gates, (uint2*)p_wgh, n4w);
        int n4o = HDIM * HDIM / 4;
        cvt_f16_kernel<<<(n4o + 255) / 256, 256>>>((const float4*)w_out, (uint2*)p_woh, n4o);
        int n4x = BSZ * HDIM / 4;
        cvt_f16_kernel<<<(n4x + 255) / 256, 256>>>((const float4*)x, (uint2*)p_xh, n4x);
    }

    // GEMM1: fused(B,2H) = x @ w_fused^T
    {
        dim3 grid(2 * HDIM / BN, BSZ / BM);
        gemm_f16_nt<<<grid, 256>>>(p_xh, p_wfh, p_fused, BSZ, 2 * HDIM, HDIM);
    }

    ew1_kernel<<<ewBlocks, ewThreads>>>(conv_state, conv_w, conv_b, out_conv_state);

    // GEMM2: gates(B,2H) = x_conv @ w_gates^T
    {
        dim3 grid(2 * HDIM / BN, BSZ / BM);
        gemm_f16_nt<<<grid, 256>>>(p_xch, p_wgh, p_gates, BSZ, 2 * HDIM, HDIM);
    }

    ew2_kernel<<<ewBlocks, ewThreads>>>(rglru_state, a_vec, out_rglru);

    // GEMM3: out(B,H) = h @ w_out^T
    {
        dim3 grid(HDIM / BN, BSZ / BM);
        gemm_f16_nt<<<grid, 256>>>(p_hh, p_woh, out_main, BSZ, HDIM, HDIM);
    }
}

// round 16
// speedup vs baseline: 1.0011x; 1.0011x over previous
#include <cuda_runtime.h>
#include <cuda_fp16.h>
#include <math.h>
#include <stdint.h>

#define BSZ 2048
#define HDIM 4096

// ---------------------------------------------------------------------------
// Scratch (allocation-free: __device__ globals)
// ---------------------------------------------------------------------------
__device__ __align__(16) __half g_wfh [(size_t)2 * HDIM * HDIM];  // fp16 w_fused
__device__ __align__(16) __half g_wgh [(size_t)2 * HDIM * HDIM];  // fp16 w_gates
__device__ __align__(16) __half g_woh [(size_t)HDIM * HDIM];      // fp16 w_out
__device__ __align__(16) __half g_xh  [(size_t)BSZ * HDIM];       // fp16 x
__device__ __align__(16) __half g_xch [(size_t)BSZ * HDIM];       // fp16 x_conv
__device__ __align__(16) __half g_hh  [(size_t)BSZ * HDIM];       // fp16 gate*state
__device__ float g_fused[(size_t)BSZ * 2 * HDIM];   // x @ w_fused^T        (fp32)
__device__ float g_gate [(size_t)BSZ * HDIM];       // gelu(gate_out)       (fp32)
__device__ float g_xconv[(size_t)BSZ * HDIM];       // conv output          (fp32)
__device__ float g_gates[(size_t)BSZ * 2 * HDIM];   // x_conv @ w_gates^T   (fp32)

// ---------------------------------------------------------------------------
// Helpers
// ---------------------------------------------------------------------------
__device__ __forceinline__ void cp_async16(uint32_t sdst, const void* gsrc) {
    asm volatile("cp.async.ca.shared.global [%0], [%1], 16;\n" :: "r"(sdst), "l"(gsrc));
}
__device__ __forceinline__ void cp_commit() {
    asm volatile("cp.async.commit_group;\n");
}
template <int N>
__device__ __forceinline__ void cp_wait() {
    asm volatile("cp.async.wait_group %0;\n" :: "n"(N));
}

// ---------------------------------------------------------------------------
// FP16 tensor-core GEMM: C[M,N] = A[M,K] @ B[N,K]^T  (fp16 in, fp32 out)
// CTA tile 128x128, BK=32, 256 threads (8 warps 4x2), warp tile 32x64,
// mma.sync.m16n8k16.f32.f16.f16.f32, cp.async double buffering.
// smem stride 40 halves (80B): fragment loads verified bank-conflict-free.
// ---------------------------------------------------------------------------
#define BM 128
#define BN 128
#define BK 32
#define SH 40   // smem stride in halves

__global__ __launch_bounds__(256, 2)
void gemm_f16_nt(const __half* __restrict__ A,
                 const __half* __restrict__ Bm,
                 float* __restrict__ C,
                 int M, int N, int K)
{
    __shared__ __half As[2][BM * SH];
    __shared__ __half Bs[2][BN * SH];

    const int tid    = threadIdx.x;
    const int lane   = tid & 31;
    const int warpId = tid >> 5;
    const int warpRow = warpId & 3;   // 0..3  (32 rows each)
    const int warpCol = warpId >> 2;  // 0..1  (64 cols each)
    const int groupID = lane >> 2;    // 0..7
    const int tid4    = lane & 3;     // 0..3

    const size_t rowBase = (size_t)blockIdx.y * BM;
    const size_t colBase = (size_t)blockIdx.x * BN;

    const __half* Ab = A  + rowBase * K;
    const __half* Bb = Bm + colBase * K;

    float acc[2][8][4];
    #pragma unroll
    for (int m = 0; m < 2; m++)
        #pragma unroll
        for (int n = 0; n < 8; n++)
            #pragma unroll
            for (int v = 0; v < 4; v++)
                acc[m][n][v] = 0.0f;

    const int numTiles = K / BK;

    uint32_t sA_base = (uint32_t)__cvta_generic_to_shared(&As[0][0]);
    uint32_t sB_base = (uint32_t)__cvta_generic_to_shared(&Bs[0][0]);
    const uint32_t stage = (uint32_t)(BM * SH * sizeof(__half));   // same for A and B

    // Per 128x32-half tile: 128 rows x 4 chunks(16B) = 512 chunks; 2/thread.
    auto issue_loads = [&](int t, int buf) {
        const int k0 = t * BK;
        #pragma unroll
        for (int i = 0; i < 2; i++) {
            int c   = tid + i * 256;      // 0..511
            int row = c >> 2;
            int j   = c & 3;              // 16B chunk = 8 halves
            cp_async16(sA_base + buf * stage + (uint32_t)(row * SH + j * 8) * 2,
                       Ab + (size_t)row * K + k0 + j * 8);
            cp_async16(sB_base + buf * stage + (uint32_t)(row * SH + j * 8) * 2,
                       Bb + (size_t)row * K + k0 + j * 8);
        }
        cp_commit();
    };

    issue_loads(0, 0);

    for (int t = 0; t < numTiles; t++) {
        const int buf = t & 1;
        if (t + 1 < numTiles) {
            issue_loads(t + 1, buf ^ 1);
            cp_wait<1>();
        } else {
            cp_wait<0>();
        }
        __syncthreads();

        const __half* sA = &As[buf][0];
        const __half* sB = &Bs[buf][0];

        #pragma unroll
        for (int kk = 0; kk < 2; kk++) {
            const int k0 = kk * 16;
            uint32_t af[2][4];
            uint32_t bf[8][2];

            #pragma unroll
            for (int m = 0; m < 2; m++) {
                int r = warpRow * 32 + m * 16 + groupID;
                af[m][0] = *reinterpret_cast<const uint32_t*>(&sA[(r)     * SH + k0 + tid4 * 2]);
                af[m][1] = *reinterpret_cast<const uint32_t*>(&sA[(r + 8) * SH + k0 + tid4 * 2]);
                af[m][2] = *reinterpret_cast<const uint32_t*>(&sA[(r)     * SH + k0 + tid4 * 2 + 8]);
                af[m][3] = *reinterpret_cast<const uint32_t*>(&sA[(r + 8) * SH + k0 + tid4 * 2 + 8]);
            }
            #pragma unroll
            for (int n = 0; n < 8; n++) {
                int cidx = warpCol * 64 + n * 8 + groupID;
                bf[n][0] = *reinterpret_cast<const uint32_t*>(&sB[cidx * SH + k0 + tid4 * 2]);
                bf[n][1] = *reinterpret_cast<const uint32_t*>(&sB[cidx * SH + k0 + tid4 * 2 + 8]);
            }

            #pragma unroll
            for (int m = 0; m < 2; m++)
                #pragma unroll
                for (int n = 0; n < 8; n++) {
                    asm volatile(
                        "mma.sync.aligned.m16n8k16.row.col.f32.f16.f16.f32 "
                        "{%0,%1,%2,%3}, {%4,%5,%6,%7}, {%8,%9}, {%0,%1,%2,%3};\n"
                        : "+f"(acc[m][n][0]), "+f"(acc[m][n][1]),
                          "+f"(acc[m][n][2]), "+f"(acc[m][n][3])
                        : "r"(af[m][0]), "r"(af[m][1]), "r"(af[m][2]), "r"(af[m][3]),
                          "r"(bf[n][0]), "r"(bf[n][1]));
                }
        }
        __syncthreads();
    }

    // Epilogue: c0,c1 -> (row, tid4*2..+1), c2,c3 -> (row+8, ...)
    #pragma unroll
    for (int m = 0; m < 2; m++) {
        size_t r0 = rowBase + warpRow * 32 + m * 16 + groupID;
        #pragma unroll
        for (int n = 0; n < 8; n++) {
            size_t cc = colBase + warpCol * 64 + n * 8 + tid4 * 2;
            *reinterpret_cast<float2*>(C + r0 * N + cc)       = make_float2(acc[m][n][0], acc[m][n][1]);
            *reinterpret_cast<float2*>(C + (r0 + 8) * N + cc) = make_float2(acc[m][n][2], acc[m][n][3]);
        }
    }
}

// ---------------------------------------------------------------------------
// Convert fp32 -> fp16 (RN), 4 elements/thread
// ---------------------------------------------------------------------------
__global__ __launch_bounds__(256)
void cvt_f16_kernel(const float4* __restrict__ in, uint2* __restrict__ out, int n4)
{
    int i = blockIdx.x * blockDim.x + threadIdx.x;
    if (i >= n4) return;
    float4 v = in[i];
    __half2 h01 = __float22half2_rn(make_float2(v.x, v.y));
    __half2 h23 = __float22half2_rn(make_float2(v.z, v.w));
    uint2 o;
    o.x = *reinterpret_cast<uint32_t*>(&h01);
    o.y = *reinterpret_cast<uint32_t*>(&h23);
    out[i] = o;
}

// ---------------------------------------------------------------------------
// Elementwise 1: gelu gate, conv step, new_conv_state; fp16 copy of x_conv
// ---------------------------------------------------------------------------
__global__ __launch_bounds__(256)
void ew1_kernel(const float* __restrict__ conv_state,
                const float* __restrict__ conv_w,
                const float* __restrict__ conv_b,
                float* __restrict__ out_conv_state)
{
    size_t idx = (size_t)blockIdx.x * blockDim.x + threadIdx.x;
    if (idx >= (size_t)BSZ * HDIM) return;
    int b = (int)(idx / HDIM);
    int h = (int)(idx % HDIM);

    const size_t frow = (size_t)b * 2 * HDIM;
    float gate_out = g_fused[frow + h];
    float x_recur  = g_fused[frow + HDIM + h];

    float gate = gate_out * 0.5f * (1.0f + erff(gate_out * 0.70710678118654752f));

    const size_t csb = (size_t)b * HDIM * 3 + (size_t)h * 3;
    float c0 = conv_state[csb + 0];
    float c1 = conv_state[csb + 1];
    float c2 = conv_state[csb + 2];

    const float* w = conv_w + (size_t)h * 4;
    float xc = fmaf(c0, w[0], fmaf(c1, w[1], fmaf(c2, w[2], fmaf(x_recur, w[3], conv_b[h]))));

    g_gate[idx]  = gate;
    g_xconv[idx] = xc;
    g_xch[idx]   = __float2half_rn(xc);

    out_conv_state[csb + 0] = c1;
    out_conv_state[csb + 1] = c2;
    out_conv_state[csb + 2] = x_recur;
}

// ---------------------------------------------------------------------------
// Elementwise 2: RG-LRU update; h = gate*state written fp16 for GEMM3
// ---------------------------------------------------------------------------
__global__ __launch_bounds__(256)
void ew2_kernel(const float* __restrict__ rglru_state,
                const float* __restrict__ a_vec,
                float* __restrict__ out_rglru_state)
{
    size_t idx = (size_t)blockIdx.x * blockDim.x + threadIdx.x;
    if (idx >= (size_t)BSZ * HDIM) return;
    int b = (int)(idx / HDIM);
    int h = (int)(idx % HDIM);

    const size_t grow = (size_t)b * 2 * HDIM;
    float gi = g_gates[grow + h];
    float gr = g_gates[grow + HDIM + h];

    float i_t = 1.0f / (1.0f + expf(-gi));
    float r_t = 1.0f / (1.0f + expf(-gr));

    float log_a = logf(a_vec[h]);
    float a_t   = expf(8.0f * r_t * log_a);
    float mult  = sqrtf(fmaxf(0.0f, 1.0f - a_t * a_t));

    float xc = g_xconv[idx];
    float new_state = fmaf(rglru_state[idx], a_t, mult * (i_t * xc));

    out_rglru_state[idx] = new_state;
    g_hh[idx] = __float2half_rn(g_gate[idx] * new_state);
}

// ---------------------------------------------------------------------------
// kernel_launch
// inputs: x, conv_state, rglru_state, w_fused, conv_w, conv_b, w_gates, a, w_out
// output: concat(out[B,H], new_conv_state[B,H,3], new_rglru_state[B,H])
// ---------------------------------------------------------------------------
extern "C" void kernel_launch(void* const* d_in, const int* in_sizes, int n_in,
                              void* d_out, int out_size)
{
    const float* x           = (const float*)d_in[0];
    const float* conv_state  = (const float*)d_in[1];
    const float* rglru_state = (const float*)d_in[2];
    const float* w_fused     = (const float*)d_in[3];
    const float* conv_w      = (const float*)d_in[4];
    const float* conv_b      = (const float*)d_in[5];
    const float* w_gates     = (const float*)d_in[6];
    const float* a_vec       = (const float*)d_in[7];
    const float* w_out       = (const float*)d_in[8];

    float* out            = (float*)d_out;
    float* out_main       = out;                                  // (B, H)
    float* out_conv_state = out + (size_t)BSZ * HDIM;             // (B, H, 3)
    float* out_rglru      = out + (size_t)BSZ * HDIM * 4;         // (B, H)

    __half *p_wfh, *p_wgh, *p_woh, *p_xh, *p_xch, *p_hh;
    float  *p_fused, *p_gates;
    cudaGetSymbolAddress((void**)&p_wfh,   g_wfh);
    cudaGetSymbolAddress((void**)&p_wgh,   g_wgh);
    cudaGetSymbolAddress((void**)&p_woh,   g_woh);
    cudaGetSymbolAddress((void**)&p_xh,    g_xh);
    cudaGetSymbolAddress((void**)&p_xch,   g_xch);
    cudaGetSymbolAddress((void**)&p_hh,    g_hh);
    cudaGetSymbolAddress((void**)&p_fused, g_fused);
    cudaGetSymbolAddress((void**)&p_gates, g_gates);

    const int ewThreads = 256;
    const int ewBlocks  = (int)(((size_t)BSZ * HDIM + ewThreads - 1) / ewThreads);

    // Convert GEMM operands to fp16 (RN)
    {
        int n4w = 2 * HDIM * HDIM / 4;
        cvt_f16_kernel<<<(n4w + 255) / 256, 256>>>((const float4*)w_fused, (uint2*)p_wfh, n4w);
        cvt_f16_kernel<<<(n4w + 255) / 256, 256>>>((const float4*)w_gates, (uint2*)p_wgh, n4w);
        int n4o = HDIM * HDIM / 4;
        cvt_f16_kernel<<<(n4o + 255) / 256, 256>>>((const float4*)w_out, (uint2*)p_woh, n4o);
        int n4x = BSZ * HDIM / 4;
        cvt_f16_kernel<<<(n4x + 255) / 256, 256>>>((const float4*)x, (uint2*)p_xh, n4x);
    }

    // GEMM1: fused(B,2H) = x @ w_fused^T
    {
        dim3 grid(2 * HDIM / BN, BSZ / BM);
        gemm_f16_nt<<<grid, 256>>>(p_xh, p_wfh, p_fused, BSZ, 2 * HDIM, HDIM);
    }

    ew1_kernel<<<ewBlocks, ewThreads>>>(conv_state, conv_w, conv_b, out_conv_state);

    // GEMM2: gates(B,2H) = x_conv @ w_gates^T
    {
        dim3 grid(2 * HDIM / BN, BSZ / BM);
        gemm_f16_nt<<<grid, 256>>>(p_xch, p_wgh, p_gates, BSZ, 2 * HDIM, HDIM);
    }

    ew2_kernel<<<ewBlocks, ewThreads>>>(rglru_state, a_vec, out_rglru);

    // GEMM3: out(B,H) = h @ w_out^T
    {
        dim3 grid(HDIM / BN, BSZ / BM);
        gemm_f16_nt<<<grid, 256>>>(p_hh, p_woh, out_main, BSZ, HDIM, HDIM);
    }
}

// round 17
// speedup vs baseline: 1.0019x; 1.0008x over previous
#include <cuda_runtime.h>
#include <cuda_fp16.h>
#include <math.h>
#include <stdint.h>

#define BSZ 2048
#define HDIM 4096

// ---------------------------------------------------------------------------
// Scratch (allocation-free: __device__ globals)
// ---------------------------------------------------------------------------
__device__ __align__(16) __half g_wfh [(size_t)2 * HDIM * HDIM];  // fp16 w_fused
__device__ __align__(16) __half g_wgh [(size_t)2 * HDIM * HDIM];  // fp16 w_gates
__device__ __align__(16) __half g_woh [(size_t)HDIM * HDIM];      // fp16 w_out
__device__ __align__(16) __half g_xh  [(size_t)BSZ * HDIM];       // fp16 x
__device__ __align__(16) __half g_xch [(size_t)BSZ * HDIM];       // fp16 x_conv
__device__ __align__(16) __half g_hh  [(size_t)BSZ * HDIM];       // fp16 gate*state
__device__ float g_fused[(size_t)BSZ * 2 * HDIM];   // x @ w_fused^T        (fp32)
__device__ float g_gate [(size_t)BSZ * HDIM];       // gelu(gate_out)       (fp32)
__device__ float g_xconv[(size_t)BSZ * HDIM];       // conv output          (fp32)
__device__ float g_gates[(size_t)BSZ * 2 * HDIM];   // x_conv @ w_gates^T   (fp32)

// ---------------------------------------------------------------------------
// Helpers
// ---------------------------------------------------------------------------
__device__ __forceinline__ void cp_async16(uint32_t sdst, const void* gsrc) {
    asm volatile("cp.async.ca.shared.global [%0], [%1], 16;\n" :: "r"(sdst), "l"(gsrc));
}
__device__ __forceinline__ void cp_commit() {
    asm volatile("cp.async.commit_group;\n");
}
template <int N>
__device__ __forceinline__ void cp_wait() {
    asm volatile("cp.async.wait_group %0;\n" :: "n"(N));
}

// ---------------------------------------------------------------------------
// FP16 tensor-core GEMM: C[M,N] = A[M,K] @ B[N,K]^T  (fp16 in, fp32 out)
// CTA tile 128x128, BK=32, 256 threads (8 warps 4x2), warp tile 32x64,
// mma.sync.m16n8k16.f32.f16.f16.f32, cp.async double buffering.
// smem stride 40 halves (80B): fragment loads verified bank-conflict-free.
// ---------------------------------------------------------------------------
#define BM 128
#define BN 128
#define BK 32
#define SH 40   // smem stride in halves

__global__ __launch_bounds__(256, 2)
void gemm_f16_nt(const __half* __restrict__ A,
                 const __half* __restrict__ Bm,
                 float* __restrict__ C,
                 int M, int N, int K)
{
    __shared__ __half As[2][BM * SH];
    __shared__ __half Bs[2][BN * SH];

    const int tid    = threadIdx.x;
    const int lane   = tid & 31;
    const int warpId = tid >> 5;
    const int warpRow = warpId & 3;   // 0..3  (32 rows each)
    const int warpCol = warpId >> 2;  // 0..1  (64 cols each)
    const int groupID = lane >> 2;    // 0..7
    const int tid4    = lane & 3;     // 0..3

    const size_t rowBase = (size_t)blockIdx.y * BM;
    const size_t colBase = (size_t)blockIdx.x * BN;

    const __half* Ab = A  + rowBase * K;
    const __half* Bb = Bm + colBase * K;

    float acc[2][8][4];
    #pragma unroll
    for (int m = 0; m < 2; m++)
        #pragma unroll
        for (int n = 0; n < 8; n++)
            #pragma unroll
            for (int v = 0; v < 4; v++)
                acc[m][n][v] = 0.0f;

    const int numTiles = K / BK;

    uint32_t sA_base = (uint32_t)__cvta_generic_to_shared(&As[0][0]);
    uint32_t sB_base = (uint32_t)__cvta_generic_to_shared(&Bs[0][0]);
    const uint32_t stage = (uint32_t)(BM * SH * sizeof(__half));   // same for A and B

    // Per 128x32-half tile: 128 rows x 4 chunks(16B) = 512 chunks; 2/thread.
    auto issue_loads = [&](int t, int buf) {
        const int k0 = t * BK;
        #pragma unroll
        for (int i = 0; i < 2; i++) {
            int c   = tid + i * 256;      // 0..511
            int row = c >> 2;
            int j   = c & 3;              // 16B chunk = 8 halves
            cp_async16(sA_base + buf * stage + (uint32_t)(row * SH + j * 8) * 2,
                       Ab + (size_t)row * K + k0 + j * 8);
            cp_async16(sB_base + buf * stage + (uint32_t)(row * SH + j * 8) * 2,
                       Bb + (size_t)row * K + k0 + j * 8);
        }
        cp_commit();
    };

    issue_loads(0, 0);

    for (int t = 0; t < numTiles; t++) {
        const int buf = t & 1;
        if (t + 1 < numTiles) {
            issue_loads(t + 1, buf ^ 1);
            cp_wait<1>();
        } else {
            cp_wait<0>();
        }
        __syncthreads();

        const __half* sA = &As[buf][0];
        const __half* sB = &Bs[buf][0];

        #pragma unroll
        for (int kk = 0; kk < 2; kk++) {
            const int k0 = kk * 16;
            uint32_t af[2][4];
            uint32_t bf[8][2];

            #pragma unroll
            for (int m = 0; m < 2; m++) {
                int r = warpRow * 32 + m * 16 + groupID;
                af[m][0] = *reinterpret_cast<const uint32_t*>(&sA[(r)     * SH + k0 + tid4 * 2]);
                af[m][1] = *reinterpret_cast<const uint32_t*>(&sA[(r + 8) * SH + k0 + tid4 * 2]);
                af[m][2] = *reinterpret_cast<const uint32_t*>(&sA[(r)     * SH + k0 + tid4 * 2 + 8]);
                af[m][3] = *reinterpret_cast<const uint32_t*>(&sA[(r + 8) * SH + k0 + tid4 * 2 + 8]);
            }
            #pragma unroll
            for (int n = 0; n < 8; n++) {
                int cidx = warpCol * 64 + n * 8 + groupID;
                bf[n][0] = *reinterpret_cast<const uint32_t*>(&sB[cidx * SH + k0 + tid4 * 2]);
                bf[n][1] = *reinterpret_cast<const uint32_t*>(&sB[cidx * SH + k0 + tid4 * 2 + 8]);
            }

            #pragma unroll
            for (int m = 0; m < 2; m++)
                #pragma unroll
                for (int n = 0; n < 8; n++) {
                    asm volatile(
                        "mma.sync.aligned.m16n8k16.row.col.f32.f16.f16.f32 "
                        "{%0,%1,%2,%3}, {%4,%5,%6,%7}, {%8,%9}, {%0,%1,%2,%3};\n"
                        : "+f"(acc[m][n][0]), "+f"(acc[m][n][1]),
                          "+f"(acc[m][n][2]), "+f"(acc[m][n][3])
                        : "r"(af[m][0]), "r"(af[m][1]), "r"(af[m][2]), "r"(af[m][3]),
                          "r"(bf[n][0]), "r"(bf[n][1]));
                }
        }
        __syncthreads();
    }

    // Epilogue: c0,c1 -> (row, tid4*2..+1), c2,c3 -> (row+8, ...)
    #pragma unroll
    for (int m = 0; m < 2; m++) {
        size_t r0 = rowBase + warpRow * 32 + m * 16 + groupID;
        #pragma unroll
        for (int n = 0; n < 8; n++) {
            size_t cc = colBase + warpCol * 64 + n * 8 + tid4 * 2;
            *reinterpret_cast<float2*>(C + r0 * N + cc)       = make_float2(acc[m][n][0], acc[m][n][1]);
            *reinterpret_cast<float2*>(C + (r0 + 8) * N + cc) = make_float2(acc[m][n][2], acc[m][n][3]);
        }
    }
}

// ---------------------------------------------------------------------------
// Convert fp32 -> fp16 (RN), 4 elements/thread
// ---------------------------------------------------------------------------
__global__ __launch_bounds__(256)
void cvt_f16_kernel(const float4* __restrict__ in, uint2* __restrict__ out, int n4)
{
    int i = blockIdx.x * blockDim.x + threadIdx.x;
    if (i >= n4) return;
    float4 v = in[i];
    __half2 h01 = __float22half2_rn(make_float2(v.x, v.y));
    __half2 h23 = __float22half2_rn(make_float2(v.z, v.w));
    uint2 o;
    o.x = *reinterpret_cast<uint32_t*>(&h01);
    o.y = *reinterpret_cast<uint32_t*>(&h23);
    out[i] = o;
}

// ---------------------------------------------------------------------------
// Elementwise 1: gelu gate, conv step, new_conv_state; fp16 copy of x_conv
// ---------------------------------------------------------------------------
__global__ __launch_bounds__(256)
void ew1_kernel(const float* __restrict__ conv_state,
                const float* __restrict__ conv_w,
                const float* __restrict__ conv_b,
                float* __restrict__ out_conv_state)
{
    size_t idx = (size_t)blockIdx.x * blockDim.x + threadIdx.x;
    if (idx >= (size_t)BSZ * HDIM) return;
    int b = (int)(idx / HDIM);
    int h = (int)(idx % HDIM);

    const size_t frow = (size_t)b * 2 * HDIM;
    float gate_out = g_fused[frow + h];
    float x_recur  = g_fused[frow + HDIM + h];

    float gate = gate_out * 0.5f * (1.0f + erff(gate_out * 0.70710678118654752f));

    const size_t csb = (size_t)b * HDIM * 3 + (size_t)h * 3;
    float c0 = conv_state[csb + 0];
    float c1 = conv_state[csb + 1];
    float c2 = conv_state[csb + 2];

    const float* w = conv_w + (size_t)h * 4;
    float xc = fmaf(c0, w[0], fmaf(c1, w[1], fmaf(c2, w[2], fmaf(x_recur, w[3], conv_b[h]))));

    g_gate[idx]  = gate;
    g_xconv[idx] = xc;
    g_xch[idx]   = __float2half_rn(xc);

    out_conv_state[csb + 0] = c1;
    out_conv_state[csb + 1] = c2;
    out_conv_state[csb + 2] = x_recur;
}

// ---------------------------------------------------------------------------
// Elementwise 2: RG-LRU update; h = gate*state written fp16 for GEMM3
// ---------------------------------------------------------------------------
__global__ __launch_bounds__(256)
void ew2_kernel(const float* __restrict__ rglru_state,
                const float* __restrict__ a_vec,
                float* __restrict__ out_rglru_state)
{
    size_t idx = (size_t)blockIdx.x * blockDim.x + threadIdx.x;
    if (idx >= (size_t)BSZ * HDIM) return;
    int b = (int)(idx / HDIM);
    int h = (int)(idx % HDIM);

    const size_t grow = (size_t)b * 2 * HDIM;
    float gi = g_gates[grow + h];
    float gr = g_gates[grow + HDIM + h];

    float i_t = 1.0f / (1.0f + expf(-gi));
    float r_t = 1.0f / (1.0f + expf(-gr));

    float log_a = logf(a_vec[h]);
    float a_t   = expf(8.0f * r_t * log_a);
    float mult  = sqrtf(fmaxf(0.0f, 1.0f - a_t * a_t));

    float xc = g_xconv[idx];
    float new_state = fmaf(rglru_state[idx], a_t, mult * (i_t * xc));

    out_rglru_state[idx] = new_state;
    g_hh[idx] = __float2half_rn(g_gate[idx] * new_state);
}

// ---------------------------------------------------------------------------
// kernel_launch
// inputs: x, conv_state, rglru_state, w_fused, conv_w, conv_b, w_gates, a, w_out
// output: concat(out[B,H], new_conv_state[B,H,3], new_rglru_state[B,H])
// ---------------------------------------------------------------------------
extern "C" void kernel_launch(void* const* d_in, const int* in_sizes, int n_in,
                              void* d_out, int out_size)
{
    const float* x           = (const float*)d_in[0];
    const float* conv_state  = (const float*)d_in[1];
    const float* rglru_state = (const float*)d_in[2];
    const float* w_fused     = (const float*)d_in[3];
    const float* conv_w      = (const float*)d_in[4];
    const float* conv_b      = (const float*)d_in[5];
    const float* w_gates     = (const float*)d_in[6];
    const float* a_vec       = (const float*)d_in[7];
    const float* w_out       = (const float*)d_in[8];

    float* out            = (float*)d_out;
    float* out_main       = out;                                  // (B, H)
    float* out_conv_state = out + (size_t)BSZ * HDIM;             // (B, H, 3)
    float* out_rglru      = out + (size_t)BSZ * HDIM * 4;         // (B, H)

    __half *p_wfh, *p_wgh, *p_woh, *p_xh, *p_xch, *p_hh;
    float  *p_fused, *p_gates;
    cudaGetSymbolAddress((void**)&p_wfh,   g_wfh);
    cudaGetSymbolAddress((void**)&p_wgh,   g_wgh);
    cudaGetSymbolAddress((void**)&p_woh,   g_woh);
    cudaGetSymbolAddress((void**)&p_xh,    g_xh);
    cudaGetSymbolAddress((void**)&p_xch,   g_xch);
    cudaGetSymbolAddress((void**)&p_hh,    g_hh);
    cudaGetSymbolAddress((void**)&p_fused, g_fused);
    cudaGetSymbolAddress((void**)&p_gates, g_gates);

    const int ewThreads = 256;
    const int ewBlocks  = (int)(((size_t)BSZ * HDIM + ewThreads - 1) / ewThreads);

    // Convert GEMM operands to fp16 (RN)
    {
        int n4w = 2 * HDIM * HDIM / 4;
        cvt_f16_kernel<<<(n4w + 255) / 256, 256>>>((const float4*)w_fused, (uint2*)p_wfh, n4w);
        cvt_f16_kernel<<<(n4w + 255) / 256, 256>>>((const float4*)w_gates, (uint2*)p_wgh, n4w);
        int n4o = HDIM * HDIM / 4;
        cvt_f16_kernel<<<(n4o + 255) / 256, 256>>>((const float4*)w_out, (uint2*)p_woh, n4o);
        int n4x = BSZ * HDIM / 4;
        cvt_f16_kernel<<<(n4x + 255) / 256, 256>>>((const float4*)x, (uint2*)p_xh, n4x);
    }

    // GEMM1: fused(B,2H) = x @ w_fused^T
    {
        dim3 grid(2 * HDIM / BN, BSZ / BM);
        gemm_f16_nt<<<grid, 256>>>(p_xh, p_wfh, p_fused, BSZ, 2 * HDIM, HDIM);
    }

    ew1_kernel<<<ewBlocks, ewThreads>>>(conv_state, conv_w, conv_b, out_conv_state);

    // GEMM2: gates(B,2H) = x_conv @ w_gates^T
    {
        dim3 grid(2 * HDIM / BN, BSZ / BM);
        gemm_f16_nt<<<grid, 256>>>(p_xch, p_wgh, p_gates, BSZ, 2 * HDIM, HDIM);
    }

    ew2_kernel<<<ewBlocks, ewThreads>>>(rglru_state, a_vec, out_rglru);

    // GEMM3: out(B,H) = h @ w_out^T
    {
        dim3 grid(HDIM / BN, BSZ / BM);
        gemm_f16_nt<<<grid, 256>>>(p_hh, p_woh, out_main, BSZ, HDIM, HDIM);
    }
}